// round 14
// baseline (speedup 1.0000x reference)
#include <cuda_runtime.h>
#include <cuda_fp16.h>
#include <math.h>
#include <stdint.h>

// Problem constants: N=100000, E=1600000, Cin=64, H=16, Cout=16, K=5
#define NCAP 100096   // multiple of 128
#define ECAP 1605632
#define NBUCK 16
#define BSH 13        // bucket = src >> 13 (8192 nodes -> 6.5MB of g_y per bucket)

// Scratch (allocation-free contract).
__device__ __half g_y[(size_t)NCAP * 400];               // per-kernel products, fp16
__device__ __align__(32) __half g_agg[(size_t)NCAP * 16]; // per-layer aggregation (fp16 RED)
__device__ float  g_deg[NCAP];                            // in-degree
__device__ float  g_rt[(size_t)NCAP * 16];                // x @ root + bias (per layer)
__device__ uint32_t g_B1[52 * 8 * 64];                    // tf32 B fragments, layer 1
__device__ uint32_t g_B2[52 * 2 * 64];                    // tf32 B fragments, layer 2
__device__ int    g_bcur[NBUCK];                          // bucket cursors
__device__ uint4  g_es[ECAP];                             // packed edges {src,dst,p0,p1}, bucketed

__device__ __forceinline__ void red_add_v4h2(__half* a, uint32_t h0, uint32_t h1,
                                             uint32_t h2, uint32_t h3) {
    asm volatile("red.global.add.noftz.v4.f16x2 [%0], {%1, %2, %3, %4};"
                 :: "l"(a), "r"(h0), "r"(h1), "r"(h2), "r"(h3) : "memory");
}
__device__ __forceinline__ uint32_t f2tf32(float f) {
    uint32_t o;
    asm("cvt.rna.tf32.f32 %0, %1;" : "=r"(o) : "f"(f));
    return o;
}
__device__ __forceinline__ void mma_tf32(float* c, const uint32_t* a, uint32_t b0, uint32_t b1) {
    asm volatile("mma.sync.aligned.m16n8k8.row.col.f32.tf32.tf32.f32 "
                 "{%0,%1,%2,%3}, {%4,%5,%6,%7}, {%8,%9}, {%0,%1,%2,%3};"
                 : "+f"(c[0]), "+f"(c[1]), "+f"(c[2]), "+f"(c[3])
                 : "r"(a[0]), "r"(a[1]), "r"(a[2]), "r"(a[3]), "r"(b0), "r"(b1));
}
__device__ __forceinline__ void cp_async16(uint32_t saddr, const void* g) {
    asm volatile("cp.async.cg.shared.global [%0], [%1], 16;" :: "r"(saddr), "l"(g));
}
#define CP_COMMIT() asm volatile("cp.async.commit_group;" ::: "memory")
#define CP_WAIT1()  asm volatile("cp.async.wait_group 1;" ::: "memory")
__device__ __forceinline__ uint32_t smem_u32(const void* p) {
    uint32_t a;
    asm("{ .reg .u64 t; cvta.to.shared.u64 t, %1; cvt.u32.u64 %0, t; }" : "=r"(a) : "l"(p));
    return a;
}

// ---------------- edge bucketing (by src range) ----------------
__global__ void bucket_zero() {
    if (threadIdx.x < NBUCK) g_bcur[threadIdx.x] = 0;
}
__global__ void bucket_hist(const int* __restrict__ src, int E) {
    __shared__ int h[NBUCK];
    if (threadIdx.x < NBUCK) h[threadIdx.x] = 0;
    __syncthreads();
    int base = blockIdx.x * 1024;
    #pragma unroll
    for (int k = 0; k < 4; k++) {
        int i = base + threadIdx.x + k * 256;
        if (i < E) atomicAdd(&h[__ldg(src + i) >> BSH], 1);
    }
    __syncthreads();
    if (threadIdx.x < NBUCK) atomicAdd(&g_bcur[threadIdx.x], h[threadIdx.x]);
}
__global__ void bucket_scan() {
    if (threadIdx.x == 0) {
        int run = 0;
        for (int b = 0; b < NBUCK; b++) { int t = g_bcur[b]; g_bcur[b] = run; run += t; }
    }
}
__global__ void bucket_fill(const int* __restrict__ src, const int* __restrict__ dst,
                            const float* __restrict__ pseudo, int E) {
    __shared__ int h[NBUCK], base[NBUCK];
    if (threadIdx.x < NBUCK) h[threadIdx.x] = 0;
    __syncthreads();
    int i0 = blockIdx.x * 1024;
    #pragma unroll
    for (int k = 0; k < 4; k++) {
        int i = i0 + threadIdx.x + k * 256;
        if (i < E) atomicAdd(&h[__ldg(src + i) >> BSH], 1);
    }
    __syncthreads();
    if (threadIdx.x < NBUCK) base[threadIdx.x] = atomicAdd(&g_bcur[threadIdx.x], h[threadIdx.x]);
    __syncthreads();
    if (threadIdx.x < NBUCK) h[threadIdx.x] = 0;
    __syncthreads();
    #pragma unroll
    for (int k = 0; k < 4; k++) {
        int i = i0 + threadIdx.x + k * 256;
        if (i < E) {
            int s = __ldg(src + i);
            int b = s >> BSH;
            int r = atomicAdd(&h[b], 1);
            float2 p = __ldg(reinterpret_cast<const float2*>(pseudo) + i);
            g_es[base[b] + r] = make_uint4((uint32_t)s, (uint32_t)__ldg(dst + i),
                                           __float_as_uint(p.x), __float_as_uint(p.y));
        }
    }
}

// Build tf32 B fragments. Logical B[n=0..415][k]: n<400 -> W[(kk*CIN+k)*16+o]
// (kk=n>>4, o=n&15); n>=400 -> root[k*16+(n-400)].
template<int CIN, int KSTEPS>
__global__ void prepB_kernel(const float* __restrict__ W, const float* __restrict__ root,
                             uint32_t* __restrict__ Bg) {
    int idx = blockIdx.x * blockDim.x + threadIdx.x;
    if (idx >= 52 * KSTEPS * 64) return;
    int ntile = idx / (KSTEPS * 64);
    int rem = idx % (KSTEPS * 64);
    int ks = rem / 64;
    int q = rem % 64;
    int lane = q >> 1;
    int reg = q & 1;
    int n = ntile * 8 + (lane >> 2);
    int k = ks * 8 + (lane & 3) + reg * 4;
    float v = 0.0f;
    if (k < CIN) {
        if (n < 400) {
            int kk = n >> 4, o = n & 15;
            v = W[(kk * CIN + k) * 16 + o];
        } else {
            v = root[k * 16 + (n - 400)];
        }
    }
    Bg[idx] = f2tf32(v);
}

// HMMA tf32 GEMM + fusions (round-10 configuration). Per CTA: M=128 nodes, N=416;
// 256 threads, 8 warps, one m16 tile per warp; 3-stage cp.async ring.
// LAYER=1: A = Xin; also zero g_agg (fp16) + g_deg for its rows.
// LAYER=2: A = relu(agg/max(deg,1) + rt) inline; then re-zero g_agg.
template<int LAYER, int KSTEPS>
__global__ void __launch_bounds__(256) gemm_kernel(const float* __restrict__ Xin,
                                                   const uint32_t* __restrict__ Bg,
                                                   const float* __restrict__ bias, int N) {
    constexpr int KC = KSTEPS * 8;
    constexpr int AP = KC + 4;
    constexpr int CHUNK_U32 = 4 * KSTEPS * 64;
    constexpr int NLD = CHUNK_U32 / 4;
    extern __shared__ uint32_t sm[];
    uint32_t* Asm = sm;                      // [128][AP]
    uint32_t* Bbuf = sm + 128 * AP;          // [3][CHUNK_U32]
    const uint32_t bbase = smem_u32(Bbuf);

    const int tid = threadIdx.x;
    const int wid = tid >> 5;
    const int lane = tid & 31;
    const int gID = lane >> 2;
    const int tig = lane & 3;
    const int n0 = blockIdx.x * 128;

    for (int i = tid; i < NLD; i += 256)
        cp_async16(bbase + i * 16, (const char*)Bg + i * 16);
    CP_COMMIT();
    for (int i = tid; i < NLD; i += 256)
        cp_async16(bbase + CHUNK_U32 * 4 + i * 16,
                   (const char*)(Bg + CHUNK_U32) + i * 16);
    CP_COMMIT();

    if (tid < 128) {
        const int n = n0 + tid;
        uint4* aggp = reinterpret_cast<uint4*>(g_agg + (size_t)n * 16);
        if (LAYER == 1) {
            const float4* xr = reinterpret_cast<const float4*>(Xin + (size_t)n * 64);
            #pragma unroll
            for (int c = 0; c < KC / 4; c++) {
                float4 f = (n < N) ? __ldg(xr + c) : make_float4(0.f, 0.f, 0.f, 0.f);
                Asm[tid * AP + 4 * c]     = f2tf32(f.x);
                Asm[tid * AP + 4 * c + 1] = f2tf32(f.y);
                Asm[tid * AP + 4 * c + 2] = f2tf32(f.z);
                Asm[tid * AP + 4 * c + 3] = f2tf32(f.w);
            }
            uint4 z = make_uint4(0u, 0u, 0u, 0u);
            aggp[0] = z; aggp[1] = z;
            g_deg[n] = 0.0f;
        } else {
            float dg = g_deg[n];
            dg = dg > 1.0f ? dg : 1.0f;
            float inv = 1.0f / dg;
            const float4* rtp = reinterpret_cast<const float4*>(g_rt + (size_t)n * 16);
            const __half2* ah = reinterpret_cast<const __half2*>(g_agg + (size_t)n * 16);
            #pragma unroll
            for (int c = 0; c < 4; c++) {
                float2 a0 = __half22float2(ah[2 * c]);
                float2 a1 = __half22float2(ah[2 * c + 1]);
                float4 rt = (n < N) ? __ldg(rtp + c) : make_float4(0.f, 0.f, 0.f, 0.f);
                float h0 = a0.x * inv + rt.x; h0 = h0 > 0.f ? h0 : 0.f;
                float h1 = a0.y * inv + rt.y; h1 = h1 > 0.f ? h1 : 0.f;
                float h2 = a1.x * inv + rt.z; h2 = h2 > 0.f ? h2 : 0.f;
                float h3 = a1.y * inv + rt.w; h3 = h3 > 0.f ? h3 : 0.f;
                Asm[tid * AP + 4 * c]     = f2tf32(h0);
                Asm[tid * AP + 4 * c + 1] = f2tf32(h1);
                Asm[tid * AP + 4 * c + 2] = f2tf32(h2);
                Asm[tid * AP + 4 * c + 3] = f2tf32(h3);
            }
            uint4 z = make_uint4(0u, 0u, 0u, 0u);
            aggp[0] = z; aggp[1] = z;
        }
    }
    __syncthreads();

    uint32_t a[KSTEPS][4];
    {
        int r0 = wid * 16 + gID;
        #pragma unroll
        for (int ks = 0; ks < KSTEPS; ks++) {
            a[ks][0] = Asm[r0 * AP + ks * 8 + tig];
            a[ks][1] = Asm[(r0 + 8) * AP + ks * 8 + tig];
            a[ks][2] = Asm[r0 * AP + ks * 8 + tig + 4];
            a[ks][3] = Asm[(r0 + 8) * AP + ks * 8 + tig + 4];
        }
    }

    #pragma unroll 1
    for (int chunk = 0; chunk < 13; chunk++) {
        CP_WAIT1();
        __syncthreads();

        const uint32_t* bb = Bbuf + (chunk % 3) * CHUNK_U32;
        float c[4][4];
        #pragma unroll
        for (int nt = 0; nt < 4; nt++)
            #pragma unroll
            for (int r = 0; r < 4; r++) c[nt][r] = 0.0f;

        #pragma unroll
        for (int ks = 0; ks < KSTEPS; ks++)
            #pragma unroll
            for (int nt = 0; nt < 4; nt++) {
                uint2 b = *reinterpret_cast<const uint2*>(bb + (nt * KSTEPS + ks) * 64 + lane * 2);
                mma_tf32(c[nt], a[ks], b.x, b.y);
            }

        #pragma unroll
        for (int nt = 0; nt < 4; nt++) {
            int col = chunk * 32 + nt * 8 + tig * 2;
            int row0 = n0 + wid * 16 + gID;
            int row1 = row0 + 8;
            float* cc = c[nt];
            if (col < 400) {
                if (row0 < N)
                    *reinterpret_cast<__half2*>(g_y + (size_t)row0 * 400 + col) =
                        __floats2half2_rn(cc[0], cc[1]);
                if (row1 < N)
                    *reinterpret_cast<__half2*>(g_y + (size_t)row1 * 400 + col) =
                        __floats2half2_rn(cc[2], cc[3]);
            } else {
                int o = col - 400;
                float bv0 = __ldg(bias + o), bv1 = __ldg(bias + o + 1);
                if (row0 < N) {
                    g_rt[(size_t)row0 * 16 + o] = cc[0] + bv0;
                    g_rt[(size_t)row0 * 16 + o + 1] = cc[1] + bv1;
                }
                if (row1 < N) {
                    g_rt[(size_t)row1 * 16 + o] = cc[2] + bv0;
                    g_rt[(size_t)row1 * 16 + o + 1] = cc[3] + bv1;
                }
            }
        }

        if (chunk + 2 < 13) {
            uint32_t dstS = bbase + ((chunk + 2) % 3) * (CHUNK_U32 * 4);
            const char* srcG = (const char*)(Bg + (size_t)(chunk + 2) * CHUNK_U32);
            for (int i = tid; i < NLD; i += 256)
                cp_async16(dstS + i * 16, srcG + i * 16);
        }
        CP_COMMIT();
    }
}

// ---------------- edge kernel: round-10 shape, reading bucketed records ----------------
// 2 lanes/edge (q = 8-channel half). One uint4 record load + 4x16B corner gathers
// + one 16B fp16 vector RED. Records are src-bucketed -> gathers are L2-resident.
__global__ void edge_kernel(int E, int addDeg) {
    int t = blockIdx.x * blockDim.x + threadIdx.x;
    int e = t >> 1;
    if (e >= E) return;
    int q = t & 1;
    uint4 ed = __ldg(g_es + e);
    int s = (int)ed.x;
    int d = (int)ed.y;
    float p0 = __uint_as_float(ed.z);
    float p1 = __uint_as_float(ed.w);
    float v0 = p0 * 4.0f, v1 = p1 * 4.0f;
    float fl0 = floorf(v0), fl1 = floorf(v1);
    float f0 = v0 - fl0, f1 = v1 - fl1;
    int i0 = (int)fl0, i1 = (int)fl1;
    int i0b = i0 + 1; if (i0b >= 5) i0b = 0;
    int i1b = i1 + 1; if (i1b >= 5) i1b = 0;
    float g0 = 1.0f - f0, g1 = 1.0f - f1;
    float w00 = g0 * g1, w10 = f0 * g1, w01 = g0 * f1, w11 = f0 * f1;

    const uint4* yb = reinterpret_cast<const uint4*>(g_y + (size_t)s * 400);
    uint4 c00 = __ldg(yb + ((i1  * 5 + i0 ) * 2 + q));
    uint4 c10 = __ldg(yb + ((i1  * 5 + i0b) * 2 + q));
    uint4 c01 = __ldg(yb + ((i1b * 5 + i0 ) * 2 + q));
    uint4 c11 = __ldg(yb + ((i1b * 5 + i0b) * 2 + q));

    uint32_t hm[4];
    #pragma unroll
    for (int j = 0; j < 4; j++) {
        float2 a = __half22float2(*reinterpret_cast<const __half2*>(((const unsigned*)&c00) + j));
        float2 b = __half22float2(*reinterpret_cast<const __half2*>(((const unsigned*)&c10) + j));
        float2 c = __half22float2(*reinterpret_cast<const __half2*>(((const unsigned*)&c01) + j));
        float2 dd = __half22float2(*reinterpret_cast<const __half2*>(((const unsigned*)&c11) + j));
        float mx = w00 * a.x + w10 * b.x + w01 * c.x + w11 * dd.x;
        float my = w00 * a.y + w10 * b.y + w01 * c.y + w11 * dd.y;
        __half2 h = __floats2half2_rn(mx, my);
        hm[j] = *reinterpret_cast<uint32_t*>(&h);
    }

    red_add_v4h2(g_agg + (size_t)d * 16 + q * 8, hm[0], hm[1], hm[2], hm[3]);
    if (addDeg && q == 0) atomicAdd(g_deg + d, 1.0f);
}

// Final output: out = agg/max(deg,1) + rt  (float4-vectorized, agg is fp16)
__global__ void node_final_kernel(float* __restrict__ out, int N) {
    int i = blockIdx.x * blockDim.x + threadIdx.x;
    if (i >= N * 4) return;
    float dg = g_deg[i >> 2];
    dg = dg > 1.0f ? dg : 1.0f;
    float inv = 1.0f / dg;
    const __half2* ah = reinterpret_cast<const __half2*>(g_agg) + i * 2;
    float2 a0 = __half22float2(ah[0]);
    float2 a1 = __half22float2(ah[1]);
    float4 rt = reinterpret_cast<const float4*>(g_rt)[i];
    float4 o;
    o.x = a0.x * inv + rt.x;
    o.y = a0.y * inv + rt.y;
    o.z = a1.x * inv + rt.z;
    o.w = a1.y * inv + rt.w;
    reinterpret_cast<float4*>(out)[i] = o;
}

extern "C" void kernel_launch(void* const* d_in, const int* in_sizes, int n_in,
                              void* d_out, int out_size) {
    const float* x      = (const float*)d_in[0];
    const int*   ei     = (const int*)  d_in[1];
    const float* pseudo = (const float*)d_in[2];
    const float* W1     = (const float*)d_in[3];
    const float* root1  = (const float*)d_in[4];
    const float* b1     = (const float*)d_in[5];
    const float* W2     = (const float*)d_in[6];
    const float* root2  = (const float*)d_in[7];
    const float* b2     = (const float*)d_in[8];
    float* out = (float*)d_out;

    int N = in_sizes[0] / 64;
    int E = in_sizes[1] / 2;
    if (N > NCAP) N = NCAP;
    if (E > ECAP) E = ECAP;
    const int* src = ei;
    const int* dst = ei + E;

    const int smem1 = 59392, smem2 = 16384;
    static uint32_t *B1p = nullptr, *B2p = nullptr;
    if (!B1p) {
        cudaGetSymbolAddress((void**)&B1p, g_B1);
        cudaGetSymbolAddress((void**)&B2p, g_B2);
        cudaFuncSetAttribute((const void*)gemm_kernel<1, 8>,
                             cudaFuncAttributeMaxDynamicSharedMemorySize, smem1);
        cudaFuncSetAttribute((const void*)gemm_kernel<2, 2>,
                             cudaFuncAttributeMaxDynamicSharedMemorySize, smem2);
    }

    int nodeGrid = (N * 4 + 255) / 256;
    int edgeGrid = (E * 2 + 255) / 256;
    int gemmGrid = (N + 127) / 128;
    int bGrid = (E + 1023) / 1024;

    // ---- Edge bucketing by src range (once; reused by both passes) ----
    bucket_zero<<<1, 32>>>();
    bucket_hist<<<bGrid, 256>>>(src, E);
    bucket_scan<<<1, 32>>>();
    bucket_fill<<<bGrid, 256>>>(src, dst, pseudo, E);

    prepB_kernel<64, 8><<<(52 * 8 * 64 + 255) / 256, 256>>>(W1, root1, B1p);
    prepB_kernel<16, 2><<<(52 * 2 * 64 + 255) / 256, 256>>>(W2, root2, B2p);
    // ---- Layer 1 (gemm zeroes agg+deg for edge pass 1) ----
    gemm_kernel<1, 8><<<gemmGrid, 256, smem1>>>(x, B1p, b1, N);
    edge_kernel<<<edgeGrid, 256>>>(E, 1);
    // ---- Layer 2 (gemm consumes layer-1 agg inline, re-zeroes agg) ----
    gemm_kernel<2, 2><<<gemmGrid, 256, smem2>>>(nullptr, B2p, b2, N);
    edge_kernel<<<edgeGrid, 256>>>(E, 0);
    node_final_kernel<<<nodeGrid, 256>>>(out, N);
}

// round 15
// speedup vs baseline: 1.1123x; 1.1123x over previous
#include <cuda_runtime.h>
#include <cuda_fp16.h>
#include <math.h>
#include <stdint.h>

// Problem constants: N=100000, E=1600000, Cin=64, H=16, Cout=16, K=5
#define NCAP 100096   // multiple of 128

// Scratch (allocation-free contract).
__device__ __half g_y[(size_t)NCAP * 400];               // per-kernel products, fp16 (80MB, L2-resident)
__device__ __align__(32) __half g_agg[(size_t)NCAP * 16]; // per-layer aggregation (fp16 RED)
__device__ float  g_deg[NCAP];                            // in-degree
__device__ float  g_rt[(size_t)NCAP * 16];                // x @ root + bias (per layer)
__device__ uint32_t g_B1[52 * 8 * 64];                    // tf32 B fragments, layer 1
__device__ uint32_t g_B2[52 * 2 * 64];                    // tf32 B fragments, layer 2

__device__ __forceinline__ void red_add_v4h2(__half* a, uint32_t h0, uint32_t h1,
                                             uint32_t h2, uint32_t h3) {
    asm volatile("red.global.add.noftz.v4.f16x2 [%0], {%1, %2, %3, %4};"
                 :: "l"(a), "r"(h0), "r"(h1), "r"(h2), "r"(h3) : "memory");
}
__device__ __forceinline__ uint32_t f2tf32(float f) {
    uint32_t o;
    asm("cvt.rna.tf32.f32 %0, %1;" : "=r"(o) : "f"(f));
    return o;
}
__device__ __forceinline__ void mma_tf32(float* c, const uint32_t* a, uint32_t b0, uint32_t b1) {
    asm volatile("mma.sync.aligned.m16n8k8.row.col.f32.tf32.tf32.f32 "
                 "{%0,%1,%2,%3}, {%4,%5,%6,%7}, {%8,%9}, {%0,%1,%2,%3};"
                 : "+f"(c[0]), "+f"(c[1]), "+f"(c[2]), "+f"(c[3])
                 : "r"(a[0]), "r"(a[1]), "r"(a[2]), "r"(a[3]), "r"(b0), "r"(b1));
}
__device__ __forceinline__ void cp_async16(uint32_t saddr, const void* g) {
    asm volatile("cp.async.cg.shared.global [%0], [%1], 16;" :: "r"(saddr), "l"(g));
}
#define CP_COMMIT() asm volatile("cp.async.commit_group;" ::: "memory")
#define CP_WAIT1()  asm volatile("cp.async.wait_group 1;" ::: "memory")
__device__ __forceinline__ uint32_t smem_u32(const void* p) {
    uint32_t a;
    asm("{ .reg .u64 t; cvta.to.shared.u64 t, %1; cvt.u32.u64 %0, t; }" : "=r"(a) : "l"(p));
    return a;
}

// Build tf32 B fragments. Logical B[n=0..415][k]: n<400 -> W[(kk*CIN+k)*16+o]
// (kk=n>>4, o=n&15); n>=400 -> root[k*16+(n-400)].
template<int CIN, int KSTEPS>
__global__ void prepB_kernel(const float* __restrict__ W, const float* __restrict__ root,
                             uint32_t* __restrict__ Bg) {
    int idx = blockIdx.x * blockDim.x + threadIdx.x;
    if (idx >= 52 * KSTEPS * 64) return;
    int ntile = idx / (KSTEPS * 64);
    int rem = idx % (KSTEPS * 64);
    int ks = rem / 64;
    int q = rem % 64;
    int lane = q >> 1;
    int reg = q & 1;
    int n = ntile * 8 + (lane >> 2);
    int k = ks * 8 + (lane & 3) + reg * 4;
    float v = 0.0f;
    if (k < CIN) {
        if (n < 400) {
            int kk = n >> 4, o = n & 15;
            v = W[(kk * CIN + k) * 16 + o];
        } else {
            v = root[k * 16 + (n - 400)];
        }
    }
    Bg[idx] = f2tf32(v);
}

// HMMA tf32 GEMM + fusions (round-10 proven config). Per CTA: M=128 nodes, N=416;
// 256 threads, 8 warps, one m16 tile per warp; 3-stage cp.async ring.
// LAYER=1: A = Xin; also zero g_agg (fp16) + g_deg for its rows.
// LAYER=2: A = relu(agg/max(deg,1) + rt) inline; then re-zero g_agg.
template<int LAYER, int KSTEPS>
__global__ void __launch_bounds__(256) gemm_kernel(const float* __restrict__ Xin,
                                                   const uint32_t* __restrict__ Bg,
                                                   const float* __restrict__ bias, int N) {
    constexpr int KC = KSTEPS * 8;
    constexpr int AP = KC + 4;
    constexpr int CHUNK_U32 = 4 * KSTEPS * 64;
    constexpr int NLD = CHUNK_U32 / 4;
    extern __shared__ uint32_t sm[];
    uint32_t* Asm = sm;                      // [128][AP]
    uint32_t* Bbuf = sm + 128 * AP;          // [3][CHUNK_U32]
    const uint32_t bbase = smem_u32(Bbuf);

    const int tid = threadIdx.x;
    const int wid = tid >> 5;
    const int lane = tid & 31;
    const int gID = lane >> 2;
    const int tig = lane & 3;
    const int n0 = blockIdx.x * 128;

    for (int i = tid; i < NLD; i += 256)
        cp_async16(bbase + i * 16, (const char*)Bg + i * 16);
    CP_COMMIT();
    for (int i = tid; i < NLD; i += 256)
        cp_async16(bbase + CHUNK_U32 * 4 + i * 16,
                   (const char*)(Bg + CHUNK_U32) + i * 16);
    CP_COMMIT();

    if (tid < 128) {
        const int n = n0 + tid;
        uint4* aggp = reinterpret_cast<uint4*>(g_agg + (size_t)n * 16);
        if (LAYER == 1) {
            const float4* xr = reinterpret_cast<const float4*>(Xin + (size_t)n * 64);
            #pragma unroll
            for (int c = 0; c < KC / 4; c++) {
                float4 f = (n < N) ? __ldg(xr + c) : make_float4(0.f, 0.f, 0.f, 0.f);
                Asm[tid * AP + 4 * c]     = f2tf32(f.x);
                Asm[tid * AP + 4 * c + 1] = f2tf32(f.y);
                Asm[tid * AP + 4 * c + 2] = f2tf32(f.z);
                Asm[tid * AP + 4 * c + 3] = f2tf32(f.w);
            }
            uint4 z = make_uint4(0u, 0u, 0u, 0u);
            aggp[0] = z; aggp[1] = z;
            g_deg[n] = 0.0f;
        } else {
            float dg = g_deg[n];
            dg = dg > 1.0f ? dg : 1.0f;
            float inv = 1.0f / dg;
            const float4* rtp = reinterpret_cast<const float4*>(g_rt + (size_t)n * 16);
            const __half2* ah = reinterpret_cast<const __half2*>(g_agg + (size_t)n * 16);
            #pragma unroll
            for (int c = 0; c < 4; c++) {
                float2 a0 = __half22float2(ah[2 * c]);
                float2 a1 = __half22float2(ah[2 * c + 1]);
                float4 rt = (n < N) ? __ldg(rtp + c) : make_float4(0.f, 0.f, 0.f, 0.f);
                float h0 = a0.x * inv + rt.x; h0 = h0 > 0.f ? h0 : 0.f;
                float h1 = a0.y * inv + rt.y; h1 = h1 > 0.f ? h1 : 0.f;
                float h2 = a1.x * inv + rt.z; h2 = h2 > 0.f ? h2 : 0.f;
                float h3 = a1.y * inv + rt.w; h3 = h3 > 0.f ? h3 : 0.f;
                Asm[tid * AP + 4 * c]     = f2tf32(h0);
                Asm[tid * AP + 4 * c + 1] = f2tf32(h1);
                Asm[tid * AP + 4 * c + 2] = f2tf32(h2);
                Asm[tid * AP + 4 * c + 3] = f2tf32(h3);
            }
            uint4 z = make_uint4(0u, 0u, 0u, 0u);
            aggp[0] = z; aggp[1] = z;
        }
    }
    __syncthreads();

    uint32_t a[KSTEPS][4];
    {
        int r0 = wid * 16 + gID;
        #pragma unroll
        for (int ks = 0; ks < KSTEPS; ks++) {
            a[ks][0] = Asm[r0 * AP + ks * 8 + tig];
            a[ks][1] = Asm[(r0 + 8) * AP + ks * 8 + tig];
            a[ks][2] = Asm[r0 * AP + ks * 8 + tig + 4];
            a[ks][3] = Asm[(r0 + 8) * AP + ks * 8 + tig + 4];
        }
    }

    #pragma unroll 1
    for (int chunk = 0; chunk < 13; chunk++) {
        CP_WAIT1();
        __syncthreads();

        const uint32_t* bb = Bbuf + (chunk % 3) * CHUNK_U32;
        float c[4][4];
        #pragma unroll
        for (int nt = 0; nt < 4; nt++)
            #pragma unroll
            for (int r = 0; r < 4; r++) c[nt][r] = 0.0f;

        #pragma unroll
        for (int ks = 0; ks < KSTEPS; ks++)
            #pragma unroll
            for (int nt = 0; nt < 4; nt++) {
                uint2 b = *reinterpret_cast<const uint2*>(bb + (nt * KSTEPS + ks) * 64 + lane * 2);
                mma_tf32(c[nt], a[ks], b.x, b.y);
            }

        #pragma unroll
        for (int nt = 0; nt < 4; nt++) {
            int col = chunk * 32 + nt * 8 + tig * 2;
            int row0 = n0 + wid * 16 + gID;
            int row1 = row0 + 8;
            float* cc = c[nt];
            if (col < 400) {
                if (row0 < N)
                    *reinterpret_cast<__half2*>(g_y + (size_t)row0 * 400 + col) =
                        __floats2half2_rn(cc[0], cc[1]);
                if (row1 < N)
                    *reinterpret_cast<__half2*>(g_y + (size_t)row1 * 400 + col) =
                        __floats2half2_rn(cc[2], cc[3]);
            } else {
                int o = col - 400;
                float bv0 = __ldg(bias + o), bv1 = __ldg(bias + o + 1);
                if (row0 < N) {
                    g_rt[(size_t)row0 * 16 + o] = cc[0] + bv0;
                    g_rt[(size_t)row0 * 16 + o + 1] = cc[1] + bv1;
                }
                if (row1 < N) {
                    g_rt[(size_t)row1 * 16 + o] = cc[2] + bv0;
                    g_rt[(size_t)row1 * 16 + o + 1] = cc[3] + bv1;
                }
            }
        }

        if (chunk + 2 < 13) {
            uint32_t dstS = bbase + ((chunk + 2) % 3) * (CHUNK_U32 * 4);
            const char* srcG = (const char*)(Bg + (size_t)(chunk + 2) * CHUNK_U32);
            for (int i = tid; i < NLD; i += 256)
                cp_async16(dstS + i * 16, srcG + i * 16);
        }
        CP_COMMIT();
    }
}

// ---------------- edge kernel: 4 lanes x 2 edges per quad ----------------
// pseudo in [0,1) => i0,i1 in {0..3}; +1 never wraps. Each edge's 4 corners are
// two contiguous 64B segments (rows i1, i1+1, 160B apart). Lane p loads 16B
// piece p of BOTH edges' two segments (4 LDG.128/thread -> MLP=4, and each LDG's
// 4-lane group covers a full 64B segment -> ~1.25 lines/edge/instr).
// fp16x2 message math; shfl_xor(2)+HADD2 folds the two i0 sides (all lanes end
// with the full sum); lanes 0,1 RED edge-a halves, lanes 2,3 RED edge-b halves.
__global__ void __launch_bounds__(256) edge_kernel(const int* __restrict__ src,
                                                   const int* __restrict__ dst,
                                                   const float* __restrict__ pseudo,
                                                   int E, int addDeg) {
    int t = blockIdx.x * blockDim.x + threadIdx.x;
    int quad = t >> 2;
    int p = t & 3;
    int e0 = quad * 2;
    bool va = (e0 < E);
    bool vb = (e0 + 1 < E);
    int ea = va ? e0 : 0;
    int eb = vb ? (e0 + 1) : 0;

    int sa = __ldg(src + ea);
    int sb = __ldg(src + eb);
    float2 pa = __ldg(reinterpret_cast<const float2*>(pseudo) + ea);
    float2 pb = __ldg(reinterpret_cast<const float2*>(pseudo) + eb);

    // decode edge a
    float va0 = pa.x * 4.0f, va1 = pa.y * 4.0f;
    float fla0 = floorf(va0), fla1 = floorf(va1);
    float fa0 = va0 - fla0, fa1 = va1 - fla1;
    int ia0 = (int)fla0, ia1 = (int)fla1;
    // decode edge b
    float vb0 = pb.x * 4.0f, vb1 = pb.y * 4.0f;
    float flb0 = floorf(vb0), flb1 = floorf(vb1);
    float fb0 = vb0 - flb0, fb1 = vb1 - flb1;
    int ib0 = (int)flb0, ib1 = (int)flb1;

    const __half* segA = g_y + (size_t)sa * 400 + (size_t)(ia1 * 5 + ia0) * 16;
    const __half* segB = g_y + (size_t)sb * 400 + (size_t)(ib1 * 5 + ib0) * 16;
    uint4 A0 = __ldg(reinterpret_cast<const uint4*>(segA) + p);        // a, row i1
    uint4 A1 = __ldg(reinterpret_cast<const uint4*>(segA + 80) + p);   // a, row i1+1
    uint4 B0 = __ldg(reinterpret_cast<const uint4*>(segB) + p);        // b, row i1
    uint4 B1 = __ldg(reinterpret_cast<const uint4*>(segB + 80) + p);   // b, row i1+1

    float ua = (p & 2) ? fa0 : (1.0f - fa0);
    __half2 waa = __float2half2_rn(ua * (1.0f - fa1));
    __half2 wab = __float2half2_rn(ua * fa1);
    float ub = (p & 2) ? fb0 : (1.0f - fb0);
    __half2 wba = __float2half2_rn(ub * (1.0f - fb1));
    __half2 wbb = __float2half2_rn(ub * fb1);

    __half2 ma[4], mb[4];
    #pragma unroll
    for (int j = 0; j < 4; j++) {
        __half2 a0h = *reinterpret_cast<const __half2*>(((const unsigned*)&A0) + j);
        __half2 a1h = *reinterpret_cast<const __half2*>(((const unsigned*)&A1) + j);
        ma[j] = __hfma2(a1h, wab, __hmul2(a0h, waa));
        __half2 b0h = *reinterpret_cast<const __half2*>(((const unsigned*)&B0) + j);
        __half2 b1h = *reinterpret_cast<const __half2*>(((const unsigned*)&B1) + j);
        mb[j] = __hfma2(b1h, wbb, __hmul2(b0h, wba));
    }

    // Fold the two i0 sides: lanes p and p^2 hold the same edge & channel-half.
    #pragma unroll
    for (int j = 0; j < 4; j++) {
        uint32_t u = *reinterpret_cast<uint32_t*>(&ma[j]);
        uint32_t v = __shfl_xor_sync(0xFFFFFFFFu, u, 2);
        ma[j] = __hadd2(ma[j], *reinterpret_cast<__half2*>(&v));
        uint32_t u2 = *reinterpret_cast<uint32_t*>(&mb[j]);
        uint32_t v2 = __shfl_xor_sync(0xFFFFFFFFu, u2, 2);
        mb[j] = __hadd2(mb[j], *reinterpret_cast<__half2*>(&v2));
    }

    // One RED per lane: lanes 0,1 -> edge a (q=p); lanes 2,3 -> edge b (q=p-2).
    bool useA = (p < 2);
    bool valid = useA ? va : vb;
    if (valid) {
        int d = __ldg(dst + (useA ? ea : eb));
        int q = p & 1;
        __half2* m = useA ? ma : mb;
        red_add_v4h2(g_agg + (size_t)d * 16 + q * 8,
                     *reinterpret_cast<uint32_t*>(&m[0]),
                     *reinterpret_cast<uint32_t*>(&m[1]),
                     *reinterpret_cast<uint32_t*>(&m[2]),
                     *reinterpret_cast<uint32_t*>(&m[3]));
        if (addDeg && q == 0) atomicAdd(g_deg + d, 1.0f);
    }
}

// Final output: out = agg/max(deg,1) + rt  (float4-vectorized, agg is fp16)
__global__ void node_final_kernel(float* __restrict__ out, int N) {
    int i = blockIdx.x * blockDim.x + threadIdx.x;
    if (i >= N * 4) return;
    float dg = g_deg[i >> 2];
    dg = dg > 1.0f ? dg : 1.0f;
    float inv = 1.0f / dg;
    const __half2* ah = reinterpret_cast<const __half2*>(g_agg) + i * 2;
    float2 a0 = __half22float2(ah[0]);
    float2 a1 = __half22float2(ah[1]);
    float4 rt = reinterpret_cast<const float4*>(g_rt)[i];
    float4 o;
    o.x = a0.x * inv + rt.x;
    o.y = a0.y * inv + rt.y;
    o.z = a1.x * inv + rt.z;
    o.w = a1.y * inv + rt.w;
    reinterpret_cast<float4*>(out)[i] = o;
}

extern "C" void kernel_launch(void* const* d_in, const int* in_sizes, int n_in,
                              void* d_out, int out_size) {
    const float* x      = (const float*)d_in[0];
    const int*   ei     = (const int*)  d_in[1];
    const float* pseudo = (const float*)d_in[2];
    const float* W1     = (const float*)d_in[3];
    const float* root1  = (const float*)d_in[4];
    const float* b1     = (const float*)d_in[5];
    const float* W2     = (const float*)d_in[6];
    const float* root2  = (const float*)d_in[7];
    const float* b2     = (const float*)d_in[8];
    float* out = (float*)d_out;

    int N = in_sizes[0] / 64;
    int E = in_sizes[1] / 2;
    if (N > NCAP) N = NCAP;
    const int* src = ei;
    const int* dst = ei + E;

    const int smem1 = 59392, smem2 = 16384;
    static uint32_t *B1p = nullptr, *B2p = nullptr;
    if (!B1p) {
        cudaGetSymbolAddress((void**)&B1p, g_B1);
        cudaGetSymbolAddress((void**)&B2p, g_B2);
        cudaFuncSetAttribute((const void*)gemm_kernel<1, 8>,
                             cudaFuncAttributeMaxDynamicSharedMemorySize, smem1);
        cudaFuncSetAttribute((const void*)gemm_kernel<2, 2>,
                             cudaFuncAttributeMaxDynamicSharedMemorySize, smem2);
    }

    int nodeGrid = (N * 4 + 255) / 256;
    int nQuads = (E + 1) / 2;
    int edgeGrid = (nQuads * 4 + 255) / 256;
    int gemmGrid = (N + 127) / 128;

    prepB_kernel<64, 8><<<(52 * 8 * 64 + 255) / 256, 256>>>(W1, root1, B1p);
    prepB_kernel<16, 2><<<(52 * 2 * 64 + 255) / 256, 256>>>(W2, root2, B2p);
    // ---- Layer 1 (gemm zeroes agg+deg for edge pass 1) ----
    gemm_kernel<1, 8><<<gemmGrid, 256, smem1>>>(x, B1p, b1, N);
    edge_kernel<<<edgeGrid, 256>>>(src, dst, pseudo, E, 1);
    // ---- Layer 2 (gemm consumes layer-1 agg inline, re-zeroes agg) ----
    gemm_kernel<2, 2><<<gemmGrid, 256, smem2>>>(nullptr, B2p, b2, N);
    edge_kernel<<<edgeGrid, 256>>>(src, dst, pseudo, E, 0);
    node_final_kernel<<<nodeGrid, 256>>>(out, N);
}